// round 14
// baseline (speedup 1.0000x reference)
#include <cuda_runtime.h>
#include <math.h>

#define BB 8
#define DD 1024
#define LOWD 512
#define SPAST 8191
#define STOT 8192
#define CPB 256           // chunks (blocks) per batch
#define CHUNK 32          // rows per block
#define NWARP 8
#define SCALE 0.02209708691207961f  // 1/sqrt(2*1024)
#define VCHUNK 64         // rows per v_copy_wv block

// ckv copy split: per-batch 8191*128 = 1048448 float4, 4 quarters of 262112,
// each quarter split across 16 blocks per batch (128 copy blocks per kernel).
#define CKV_F4_PER_B   1048448
#define CKV_QF4        262112
#define CKV_PER_BLOCK  16382
#define NCOPY          128

// ------------------- device scratch (no allocations allowed) -------------------
__device__ float g_cur_ckv[BB*LOWD];
__device__ float g_cur_kr [BB*DD];
__device__ float g_cur_up [BB*2*DD];
__device__ float g_Cq  [BB*DD];
__device__ float g_Qc  [BB*DD];
__device__ float g_Qr  [BB*DD];
__device__ float g_score[BB*STOT];
__device__ float g_w    [BB*STOT];
__device__ float g_attn [BB*DD];

// ------------------- ckv copy quarter helper -------------------
// k in [0, NCOPY): b = k/16, sub = k%16. Copies 16382 float4 of quarter q.
__device__ __forceinline__ void ckv_copy_part(const float* __restrict__ ckv_cache,
                                              float* __restrict__ out_ckv,
                                              int q, int k) {
    int b   = k >> 4;
    int sub = k & 15;
    size_t start = (size_t)q * CKV_QF4 + (size_t)sub * CKV_PER_BLOCK;
    size_t end   = start + CKV_PER_BLOCK;
    const float4* src = (const float4*)ckv_cache + (size_t)b * CKV_F4_PER_B;
    float4*       dst = (float4*)out_ckv + (size_t)b * (STOT * LOWD / 4);
#pragma unroll 4
    for (size_t i = start + threadIdx.x; i < end; i += 256)
        __stcs(dst + i, __ldcs(src + i));
}

// ------------------- zero scratch + out_att region + ckv copy q0 -------------------
__global__ void zero_scratch(const float* __restrict__ ckv_cache,
                             float* __restrict__ out_ckv, float* __restrict__ dout) {
    if (blockIdx.x >= 64) { ckv_copy_part(ckv_cache, out_ckv, 0, blockIdx.x - 64); return; }
    int i = blockIdx.x * 256 + threadIdx.x;           // covers 16384
    if (i < BB*LOWD)  g_cur_ckv[i] = 0.f;
    if (i < BB*DD) { g_cur_kr[i] = 0.f; g_Cq[i] = 0.f; g_Qc[i] = 0.f;
                     g_Qr[i] = 0.f; g_attn[i] = 0.f; }
    if (i < BB*2*DD)  g_cur_up[i] = 0.f;
    if (i < BB*DD)    dout[i] = 0.f;
}

// ------------------- stage 1: [cur_ckv | cur_kr | Cq] = x @ [Wdkv | Wkr | Wdq] --------
// 1-D grid: 320 proj blocks (10 x-tiles × 32 d-splits) + 128 ckv-copy q1 blocks.
__global__ void proj1(const float* __restrict__ x,
                      const float* __restrict__ Wdkv, const float* __restrict__ Wkr,
                      const float* __restrict__ Wdq,
                      const float* __restrict__ ckv_cache, float* __restrict__ out_ckv) {
    if (blockIdx.x >= 320) { ckv_copy_part(ckv_cache, out_ckv, 1, blockIdx.x - 320); return; }
    __shared__ float sx[BB * 32];
    int bx = blockIdx.x % 10, by = blockIdx.x / 10;
    int og = bx * 256 + threadIdx.x;                 // 0..2559
    int d0 = by * 32;
    if (threadIdx.x < BB * 32) {
        int b = threadIdx.x >> 5, dd = threadIdx.x & 31;
        sx[threadIdx.x] = x[b * DD + d0 + dd];
    }
    __syncthreads();
    const float* W; float* Y; int O; int col;
    if (og < 512)       { W = Wdkv; Y = g_cur_ckv; O = LOWD; col = og; }
    else if (og < 1536) { W = Wkr;  Y = g_cur_kr;  O = DD;   col = og - 512; }
    else                { W = Wdq;  Y = g_Cq;      O = DD;   col = og - 1536; }
    float acc[BB];
#pragma unroll
    for (int b = 0; b < BB; b++) acc[b] = 0.f;
#pragma unroll
    for (int dd = 0; dd < 32; dd++) {
        float w = W[(size_t)(d0 + dd) * O + col];
#pragma unroll
        for (int b = 0; b < BB; b++) acc[b] = fmaf(sx[(b << 5) + dd], w, acc[b]);
    }
#pragma unroll
    for (int b = 0; b < BB; b++) atomicAdd(&Y[b * O + col], acc[b]);
}

// ------------------- stage 2: [Qc | Qr] = Cq @ [Wuq|Wqr]; cur_up = cur_ckv @ fup -------
// 1-D grid: 512 proj blocks (16 x-tiles × 32 d-splits) + 128 ckv-copy q2 blocks.
__global__ void proj2(const float* __restrict__ Wuq, const float* __restrict__ Wqr,
                      const float* __restrict__ fup,
                      const float* __restrict__ ckv_cache, float* __restrict__ out_ckv) {
    if (blockIdx.x >= 512) { ckv_copy_part(ckv_cache, out_ckv, 2, blockIdx.x - 512); return; }
    __shared__ float sx[BB * 32];
    int bx = blockIdx.x & 15, by = blockIdx.x >> 4;
    int og = bx * 256 + threadIdx.x;                 // 0..4095
    const float* W; const float* X; float* Y; int O, col, Din;
    if (og < 1024)      { W = Wuq; X = g_Cq;      Y = g_Qc;     O = DD;     col = og;        Din = DD;   }
    else if (og < 2048) { W = Wqr; X = g_Cq;      Y = g_Qr;     O = DD;     col = og - 1024; Din = DD;   }
    else                { W = fup; X = g_cur_ckv; Y = g_cur_up; O = 2 * DD; col = og - 2048; Din = LOWD; }
    int dchunk = Din >> 5;                            // 32 or 16
    int d0 = by * dchunk;
    if (threadIdx.x < BB * dchunk) {
        int b = threadIdx.x / dchunk, dd = threadIdx.x - b * dchunk;
        sx[b * dchunk + dd] = X[b * Din + d0 + dd];
    }
    __syncthreads();
    float acc[BB];
#pragma unroll
    for (int b = 0; b < BB; b++) acc[b] = 0.f;
#pragma unroll 16
    for (int dd = 0; dd < dchunk; dd++) {
        float w = W[(size_t)(d0 + dd) * O + col];
#pragma unroll
        for (int b = 0; b < BB; b++) acc[b] = fmaf(sx[b * dchunk + dd], w, acc[b]);
    }
#pragma unroll
    for (int b = 0; b < BB; b++) atomicAdd(&Y[b * O + col], acc[b]);
}

// ------------------- streaming kernel: kr/k_up copy + raw scores (no ckv, no v) --------
// 4-deep load batching (R11 operating point).
__global__ void __launch_bounds__(256)
stream_score(const float* __restrict__ kr_cache, const float* __restrict__ up_cache,
             float* __restrict__ out_kr, float* __restrict__ out_up) {
    __shared__ float4 sqc[DD / 4];                   // 4 KB
    __shared__ float4 sqr[DD / 4];                   // 4 KB
    int b    = blockIdx.x / CPB;
    int c    = blockIdx.x % CPB;
    int warp = threadIdx.x >> 5;
    int lane = threadIdx.x & 31;
    int s0   = c * CHUNK;
    int rows = SPAST - s0; if (rows > CHUNK) rows = CHUNK;

    // --- q into shared ---
    sqc[threadIdx.x] = ((const float4*)(g_Qc + b * DD))[threadIdx.x];
    sqr[threadIdx.x] = ((const float4*)(g_Qr + b * DD))[threadIdx.x];
    __syncthreads();

    // --- per-warp rows: k_up + kr copy + dot (4-deep explicit load batching) ---
    for (int i = warp; i < rows; i += NWARP) {
        int s = s0 + i;
        const float4* u4 = (const float4*)(up_cache + ((size_t)b * SPAST + s) * 2 * DD);
        const float4* k4 = (const float4*)(kr_cache + ((size_t)b * SPAST + s) * DD);
        float4* ou4 = (float4*)(out_up + ((size_t)b * STOT + s) * 2 * DD);
        float4* ok4 = (float4*)(out_kr + ((size_t)b * STOT + s) * DD);

        float part = 0.f;
#pragma unroll
        for (int h = 0; h < 2; h++) {                // k_up half: 2 batches of 4
            float4 t[4];
#pragma unroll
            for (int j = 0; j < 4; j++) t[j] = __ldcs(u4 + lane + 32 * (4 * h + j));
#pragma unroll
            for (int j = 0; j < 4; j++) {
                __stcs(ou4 + lane + 32 * (4 * h + j), t[j]);
                float4 q = sqc[lane + 32 * (4 * h + j)];
                part += t[j].x * q.x + t[j].y * q.y + t[j].z * q.z + t[j].w * q.w;
            }
        }
#pragma unroll
        for (int h = 0; h < 2; h++) {                // kr: 2 batches of 4
            float4 t[4];
#pragma unroll
            for (int j = 0; j < 4; j++) t[j] = __ldcs(k4 + lane + 32 * (4 * h + j));
#pragma unroll
            for (int j = 0; j < 4; j++) {
                __stcs(ok4 + lane + 32 * (4 * h + j), t[j]);
                float4 q = sqr[lane + 32 * (4 * h + j)];
                part += t[j].x * q.x + t[j].y * q.y + t[j].z * q.z + t[j].w * q.w;
            }
        }
#pragma unroll
        for (int off = 16; off; off >>= 1) part += __shfl_xor_sync(0xffffffffu, part, off);
        if (lane == 0) g_score[b * STOT + s] = part * SCALE;
    }
}

// ------------------- current token rows + cur score + softmax + ckv copy q3 ------------
__global__ void fin_softmax(float* __restrict__ out_ckv, float* __restrict__ out_kr,
                            float* __restrict__ out_up,
                            const float* __restrict__ ckv_cache) {
    if (blockIdx.x >= 8) { ckv_copy_part(ckv_cache, out_ckv, 3, blockIdx.x - 8); return; }
    int b = blockIdx.x, tid = threadIdx.x;
    // copy new rows into position s = SPAST
    {
        const float4* cc = (const float4*)(g_cur_ckv + b * LOWD);
        float4* oc = (float4*)(out_ckv + ((size_t)b * STOT + SPAST) * LOWD);
        for (int i = tid; i < LOWD / 4; i += 256) oc[i] = cc[i];
        const float4* ck = (const float4*)(g_cur_kr + b * DD);
        float4* ok = (float4*)(out_kr + ((size_t)b * STOT + SPAST) * DD);
        for (int i = tid; i < DD / 4; i += 256) ok[i] = ck[i];
        const float4* cu = (const float4*)(g_cur_up + b * 2 * DD);
        float4* ou = (float4*)(out_up + ((size_t)b * STOT + SPAST) * 2 * DD);
        for (int i = tid; i < 2 * DD / 4; i += 256) ou[i] = cu[i];
    }
    // current-token raw score
    float part = 0.f;
    for (int i = tid; i < DD; i += 256) part += g_Qc[b * DD + i] * g_cur_up[b * 2 * DD + i];
    for (int i = tid; i < DD; i += 256) part += g_Qr[b * DD + i] * g_cur_kr[b * DD + i];
    __shared__ float sred[256];
    __shared__ float sM, sL;
    sred[tid] = part; __syncthreads();
    for (int s = 128; s; s >>= 1) { if (tid < s) sred[tid] += sred[tid + s]; __syncthreads(); }
    if (tid == 0) g_score[b * STOT + SPAST] = sred[0] * SCALE;
    __syncthreads();
    // exact softmax over all 8192 scores
    float M = -1e30f;
    for (int i = tid; i < STOT; i += 256) M = fmaxf(M, g_score[b * STOT + i]);
    sred[tid] = M; __syncthreads();
    for (int s = 128; s; s >>= 1) { if (tid < s) sred[tid] = fmaxf(sred[tid], sred[tid + s]); __syncthreads(); }
    if (tid == 0) sM = sred[0];
    __syncthreads();
    M = sM;
    float L = 0.f;
    for (int i = tid; i < STOT; i += 256) {
        float e = __expf(g_score[b * STOT + i] - M);
        g_w[b * STOT + i] = e;
        L += e;
    }
    sred[tid] = L; __syncthreads();
    for (int s = 128; s; s >>= 1) { if (tid < s) sred[tid] += sred[tid + s]; __syncthreads(); }
    if (tid == 0) sL = sred[0];
    __syncthreads();
    float inv = 1.f / sL;
    for (int i = tid; i < STOT; i += 256) g_w[b * STOT + i] *= inv;
}

// ------------------- v copy + attn accumulation fused (post-softmax) --------------------
// grid (BB, STOT/VCHUNK) = (8, 128). 8-deep load batching; 4 CTAs/SM pinned.
__global__ void __launch_bounds__(256, 4)
v_copy_wv(const float* __restrict__ up_cache, float* __restrict__ out_up) {
    __shared__ float sw[VCHUNK];
    int b = blockIdx.x, tid = threadIdx.x;
    int s0 = blockIdx.y * VCHUNK;
    if (tid < VCHUNK) sw[tid] = g_w[b * STOT + s0 + tid];
    __syncthreads();
    int rows = SPAST - s0; if (rows > VCHUNK) rows = VCHUNK;   // last block: 63 cache rows
    const float4* src = (const float4*)(up_cache + ((size_t)b * SPAST + s0) * 2 * DD) + 256 + tid;
    float4*       dst = (float4*)(out_up + ((size_t)b * STOT + s0) * 2 * DD) + 256 + tid;

    float4 a0 = make_float4(0.f,0.f,0.f,0.f), a1 = a0, a2 = a0, a3 = a0;
    int r = 0;
    for (; r + 8 <= rows; r += 8) {
        float4 v[8];
#pragma unroll
        for (int j = 0; j < 8; j++) v[j] = __ldcs(src + (size_t)(r + j) * 512);
#pragma unroll
        for (int j = 0; j < 8; j++) __stcs(dst + (size_t)(r + j) * 512, v[j]);
#pragma unroll
        for (int j = 0; j < 4; j++) {
            float wa = sw[r + 2 * j], wb = sw[r + 2 * j + 1];
            float4 va = v[2 * j], vb = v[2 * j + 1];
            float4* A = (j == 0) ? &a0 : (j == 1) ? &a1 : (j == 2) ? &a2 : &a3;
            A->x = fmaf(wa, va.x, A->x); A->y = fmaf(wa, va.y, A->y);
            A->z = fmaf(wa, va.z, A->z); A->w = fmaf(wa, va.w, A->w);
            A->x = fmaf(wb, vb.x, A->x); A->y = fmaf(wb, vb.y, A->y);
            A->z = fmaf(wb, vb.z, A->z); A->w = fmaf(wb, vb.w, A->w);
        }
    }
    for (; r < rows; r++) {
        float4 v = __ldcs(src + (size_t)r * 512);
        __stcs(dst + (size_t)r * 512, v);
        float w = sw[r];
        a0.x = fmaf(w, v.x, a0.x); a0.y = fmaf(w, v.y, a0.y);
        a0.z = fmaf(w, v.z, a0.z); a0.w = fmaf(w, v.w, a0.w);
    }
    // current-token row (v already copied to out_up by fin_softmax; read from scratch)
    if (s0 + VCHUNK > SPAST) {
        float w = sw[SPAST - s0];
        float4 v = ((const float4*)(g_cur_up + b * 2 * DD + DD))[tid];
        a0.x = fmaf(w, v.x, a0.x); a0.y = fmaf(w, v.y, a0.y);
        a0.z = fmaf(w, v.z, a0.z); a0.w = fmaf(w, v.w, a0.w);
    }
    float4 a;
    a.x = (a0.x + a1.x) + (a2.x + a3.x);
    a.y = (a0.y + a1.y) + (a2.y + a3.y);
    a.z = (a0.z + a1.z) + (a2.z + a3.z);
    a.w = (a0.w + a1.w) + (a2.w + a3.w);
    float* dstA = g_attn + b * DD + 4 * tid;
    atomicAdd(dstA + 0, a.x);
    atomicAdd(dstA + 1, a.y);
    atomicAdd(dstA + 2, a.z);
    atomicAdd(dstA + 3, a.w);
}

// ------------------- out = attn @ Wo -------------------
// grid (4, 32): 1024 outputs tiled by 256; Din split 32.
__global__ void gemv_wo(const float* __restrict__ Wo, float* __restrict__ Y) {
    __shared__ float sx[BB * 32];
    int o = blockIdx.x * 256 + threadIdx.x;
    int d0 = blockIdx.y * 32;
    if (threadIdx.x < BB * 32) {
        int b = threadIdx.x >> 5, dd = threadIdx.x & 31;
        sx[threadIdx.x] = g_attn[b * DD + d0 + dd];
    }
    __syncthreads();
    float acc[BB];
#pragma unroll
    for (int b = 0; b < BB; b++) acc[b] = 0.f;
#pragma unroll
    for (int dd = 0; dd < 32; dd++) {
        float w = Wo[(size_t)(d0 + dd) * DD + o];
#pragma unroll
        for (int b = 0; b < BB; b++) acc[b] = fmaf(sx[(b << 5) + dd], w, acc[b]);
    }
#pragma unroll
    for (int b = 0; b < BB; b++) atomicAdd(&Y[b * DD + o], acc[b]);
}

// ------------------- launch -------------------
extern "C" void kernel_launch(void* const* d_in, const int* in_sizes, int n_in,
                              void* d_out, int out_size) {
    (void)in_sizes; (void)n_in; (void)out_size;
    const float* x        = (const float*)d_in[0];
    const float* ckv_c    = (const float*)d_in[1];
    const float* kr_c     = (const float*)d_in[2];
    const float* up_c     = (const float*)d_in[3];
    const float* Wdq      = (const float*)d_in[4];
    const float* Wuq      = (const float*)d_in[5];
    const float* Wqr      = (const float*)d_in[6];
    const float* Wdkv     = (const float*)d_in[7];
    const float* Wkr      = (const float*)d_in[8];
    const float* fup      = (const float*)d_in[9];
    const float* Wo       = (const float*)d_in[10];

    float* dout    = (float*)d_out;
    float* out_att = dout;                                     // [8,1,1024]
    float* out_ckv = dout + (size_t)BB * DD;                   // [8,8192,512]
    float* out_kr  = out_ckv + (size_t)BB * STOT * LOWD;       // [8,8192,1024]
    float* out_up  = out_kr  + (size_t)BB * STOT * DD;         // [8,8192,2048]

    // zero + ckv copy q0
    zero_scratch<<<64 + NCOPY, 256>>>(ckv_c, out_ckv, dout);

    // projection chain, each with a ckv copy quarter riding along
    proj1<<<320 + NCOPY, 256>>>(x, Wdkv, Wkr, Wdq, ckv_c, out_ckv);
    proj2<<<512 + NCOPY, 256>>>(Wuq, Wqr, fup, ckv_c, out_ckv);

    // streaming pass: kr/k_up copies + raw scores (ckv + v handled elsewhere)
    stream_score<<<BB * CPB, 256>>>(kr_c, up_c, out_kr, out_up);

    // current-token rows + cur score + softmax + ckv copy q3
    fin_softmax<<<8 + NCOPY, 256>>>(out_ckv, out_kr, out_up, ckv_c);

    // v copy + attn accumulation in one pass (reads v exactly once)
    v_copy_wv<<<dim3(BB, STOT / VCHUNK), 256>>>(up_c, out_up);

    // out = attn @ Wo
    gemv_wo<<<dim3(4, 32), 256>>>(Wo, out_att);
}

// round 15
// speedup vs baseline: 1.2381x; 1.2381x over previous
#include <cuda_runtime.h>
#include <math.h>

#define BB 8
#define DD 1024
#define LOWD 512
#define SPAST 8191
#define STOT 8192
#define CPB 256           // chunks (blocks) per batch
#define CHUNK 32          // rows per block
#define NWARP 8
#define SCALE 0.02209708691207961f  // 1/sqrt(2*1024)
#define VCHUNK 64         // rows per v_copy_wv block

// ckv copy: per-batch 8191*128 = 1048448 float4, split 64 blocks per batch.
#define CKV_F4_PER_B   1048448
#define CKV_PER_BLOCK  16382      // 64 * 16382 = 1048448
#define CKV_NSUB       64

// ------------------- device scratch (no allocations allowed) -------------------
__device__ float g_cur_ckv[BB*LOWD];
__device__ float g_cur_kr [BB*DD];
__device__ float g_cur_up [BB*2*DD];
__device__ float g_Cq  [BB*DD];
__device__ float g_Qc  [BB*DD];
__device__ float g_Qr  [BB*DD];
__device__ float g_score[BB*STOT];
__device__ float g_w    [BB*STOT];
__device__ float g_attn [BB*DD];

// ------------------- zero scratch + out_att region -------------------
__global__ void zero_scratch(float* __restrict__ dout) {
    int i = blockIdx.x * 256 + threadIdx.x;           // grid: 64*256 = 16384
    if (i < BB*LOWD)  g_cur_ckv[i] = 0.f;
    if (i < BB*DD) { g_cur_kr[i] = 0.f; g_Cq[i] = 0.f; g_Qc[i] = 0.f;
                     g_Qr[i] = 0.f; g_attn[i] = 0.f; }
    if (i < BB*2*DD)  g_cur_up[i] = 0.f;
    if (i < BB*DD)    dout[i] = 0.f;
}

// ------------------- stage 1: [cur_ckv | cur_kr | Cq] = x @ [Wdkv | Wkr | Wdq] --------
// grid (10, 32): 2560 outputs tiled by 256; Din=1024 split 32 (32 each); atomic accum.
__global__ void proj1(const float* __restrict__ x,
                      const float* __restrict__ Wdkv, const float* __restrict__ Wkr,
                      const float* __restrict__ Wdq) {
    __shared__ float sx[BB * 32];
    int og = blockIdx.x * 256 + threadIdx.x;         // 0..2559
    int d0 = blockIdx.y * 32;
    if (threadIdx.x < BB * 32) {
        int b = threadIdx.x >> 5, dd = threadIdx.x & 31;
        sx[threadIdx.x] = x[b * DD + d0 + dd];
    }
    __syncthreads();
    const float* W; float* Y; int O; int col;
    if (og < 512)       { W = Wdkv; Y = g_cur_ckv; O = LOWD; col = og; }
    else if (og < 1536) { W = Wkr;  Y = g_cur_kr;  O = DD;   col = og - 512; }
    else                { W = Wdq;  Y = g_Cq;      O = DD;   col = og - 1536; }
    float acc[BB];
#pragma unroll
    for (int b = 0; b < BB; b++) acc[b] = 0.f;
#pragma unroll
    for (int dd = 0; dd < 32; dd++) {
        float w = W[(size_t)(d0 + dd) * O + col];
#pragma unroll
        for (int b = 0; b < BB; b++) acc[b] = fmaf(sx[(b << 5) + dd], w, acc[b]);
    }
#pragma unroll
    for (int b = 0; b < BB; b++) atomicAdd(&Y[b * O + col], acc[b]);
}

// ------------------- stage 2: [Qc | Qr] = Cq @ [Wuq|Wqr]; cur_up = cur_ckv @ fup -------
// grid (16, 32): 4096 outputs tiled by 256. Ranges align to block boundaries.
__global__ void proj2(const float* __restrict__ Wuq, const float* __restrict__ Wqr,
                      const float* __restrict__ fup) {
    __shared__ float sx[BB * 32];
    int og = blockIdx.x * 256 + threadIdx.x;         // 0..4095
    const float* W; const float* X; float* Y; int O, col, Din;
    if (og < 1024)      { W = Wuq; X = g_Cq;      Y = g_Qc;     O = DD;     col = og;        Din = DD;   }
    else if (og < 2048) { W = Wqr; X = g_Cq;      Y = g_Qr;     O = DD;     col = og - 1024; Din = DD;   }
    else                { W = fup; X = g_cur_ckv; Y = g_cur_up; O = 2 * DD; col = og - 2048; Din = LOWD; }
    int dchunk = Din >> 5;                            // 32 or 16
    int d0 = blockIdx.y * dchunk;
    if (threadIdx.x < BB * dchunk) {
        int b = threadIdx.x / dchunk, dd = threadIdx.x - b * dchunk;
        sx[b * dchunk + dd] = X[b * Din + d0 + dd];
    }
    __syncthreads();
    float acc[BB];
#pragma unroll
    for (int b = 0; b < BB; b++) acc[b] = 0.f;
#pragma unroll 16
    for (int dd = 0; dd < dchunk; dd++) {
        float w = W[(size_t)(d0 + dd) * O + col];
#pragma unroll
        for (int b = 0; b < BB; b++) acc[b] = fmaf(sx[b * dchunk + dd], w, acc[b]);
    }
#pragma unroll
    for (int b = 0; b < BB; b++) atomicAdd(&Y[b * O + col], acc[b]);
}

// ------------------- streaming kernel: kr/k_up copy + raw scores (no ckv, no v) --------
// 4-deep load batching (R11 operating point; 82.8% DRAM in R14).
__global__ void __launch_bounds__(256)
stream_score(const float* __restrict__ kr_cache, const float* __restrict__ up_cache,
             float* __restrict__ out_kr, float* __restrict__ out_up) {
    __shared__ float4 sqc[DD / 4];                   // 4 KB
    __shared__ float4 sqr[DD / 4];                   // 4 KB
    int b    = blockIdx.x / CPB;
    int c    = blockIdx.x % CPB;
    int warp = threadIdx.x >> 5;
    int lane = threadIdx.x & 31;
    int s0   = c * CHUNK;
    int rows = SPAST - s0; if (rows > CHUNK) rows = CHUNK;

    // --- q into shared ---
    sqc[threadIdx.x] = ((const float4*)(g_Qc + b * DD))[threadIdx.x];
    sqr[threadIdx.x] = ((const float4*)(g_Qr + b * DD))[threadIdx.x];
    __syncthreads();

    // --- per-warp rows: k_up + kr copy + dot (4-deep explicit load batching) ---
    for (int i = warp; i < rows; i += NWARP) {
        int s = s0 + i;
        const float4* u4 = (const float4*)(up_cache + ((size_t)b * SPAST + s) * 2 * DD);
        const float4* k4 = (const float4*)(kr_cache + ((size_t)b * SPAST + s) * DD);
        float4* ou4 = (float4*)(out_up + ((size_t)b * STOT + s) * 2 * DD);
        float4* ok4 = (float4*)(out_kr + ((size_t)b * STOT + s) * DD);

        float part = 0.f;
#pragma unroll
        for (int h = 0; h < 2; h++) {                // k_up half: 2 batches of 4
            float4 t[4];
#pragma unroll
            for (int j = 0; j < 4; j++) t[j] = __ldcs(u4 + lane + 32 * (4 * h + j));
#pragma unroll
            for (int j = 0; j < 4; j++) {
                __stcs(ou4 + lane + 32 * (4 * h + j), t[j]);
                float4 q = sqc[lane + 32 * (4 * h + j)];
                part += t[j].x * q.x + t[j].y * q.y + t[j].z * q.z + t[j].w * q.w;
            }
        }
#pragma unroll
        for (int h = 0; h < 2; h++) {                // kr: 2 batches of 4
            float4 t[4];
#pragma unroll
            for (int j = 0; j < 4; j++) t[j] = __ldcs(k4 + lane + 32 * (4 * h + j));
#pragma unroll
            for (int j = 0; j < 4; j++) {
                __stcs(ok4 + lane + 32 * (4 * h + j), t[j]);
                float4 q = sqr[lane + 32 * (4 * h + j)];
                part += t[j].x * q.x + t[j].y * q.y + t[j].z * q.z + t[j].w * q.w;
            }
        }
#pragma unroll
        for (int off = 16; off; off >>= 1) part += __shfl_xor_sync(0xffffffffu, part, off);
        if (lane == 0) g_score[b * STOT + s] = part * SCALE;
    }
}

// ------------------- current token rows + cur score + exact softmax (merged) ------------
__global__ void fin_softmax(float* __restrict__ out_ckv, float* __restrict__ out_kr,
                            float* __restrict__ out_up) {
    int b = blockIdx.x, tid = threadIdx.x;
    // copy new rows into position s = SPAST
    {
        const float4* cc = (const float4*)(g_cur_ckv + b * LOWD);
        float4* oc = (float4*)(out_ckv + ((size_t)b * STOT + SPAST) * LOWD);
        for (int i = tid; i < LOWD / 4; i += 256) oc[i] = cc[i];
        const float4* ck = (const float4*)(g_cur_kr + b * DD);
        float4* ok = (float4*)(out_kr + ((size_t)b * STOT + SPAST) * DD);
        for (int i = tid; i < DD / 4; i += 256) ok[i] = ck[i];
        const float4* cu = (const float4*)(g_cur_up + b * 2 * DD);
        float4* ou = (float4*)(out_up + ((size_t)b * STOT + SPAST) * 2 * DD);
        for (int i = tid; i < 2 * DD / 4; i += 256) ou[i] = cu[i];
    }
    // current-token raw score
    float part = 0.f;
    for (int i = tid; i < DD; i += 256) part += g_Qc[b * DD + i] * g_cur_up[b * 2 * DD + i];
    for (int i = tid; i < DD; i += 256) part += g_Qr[b * DD + i] * g_cur_kr[b * DD + i];
    __shared__ float sred[256];
    __shared__ float sM, sL;
    sred[tid] = part; __syncthreads();
    for (int s = 128; s; s >>= 1) { if (tid < s) sred[tid] += sred[tid + s]; __syncthreads(); }
    if (tid == 0) g_score[b * STOT + SPAST] = sred[0] * SCALE;
    __syncthreads();
    // exact softmax over all 8192 scores
    float M = -1e30f;
    for (int i = tid; i < STOT; i += 256) M = fmaxf(M, g_score[b * STOT + i]);
    sred[tid] = M; __syncthreads();
    for (int s = 128; s; s >>= 1) { if (tid < s) sred[tid] = fmaxf(sred[tid], sred[tid + s]); __syncthreads(); }
    if (tid == 0) sM = sred[0];
    __syncthreads();
    M = sM;
    float L = 0.f;
    for (int i = tid; i < STOT; i += 256) {
        float e = __expf(g_score[b * STOT + i] - M);
        g_w[b * STOT + i] = e;
        L += e;
    }
    sred[tid] = L; __syncthreads();
    for (int s = 128; s; s >>= 1) { if (tid < s) sred[tid] += sred[tid + s]; __syncthreads(); }
    if (tid == 0) sL = sred[0];
    __syncthreads();
    float inv = 1.f / sL;
    for (int i = tid; i < STOT; i += 256) g_w[b * STOT + i] *= inv;
}

// ------------------- v copy + w·v accumulation + ckv copy (one saturated kernel) -------
// grid (BB, 128 + CKV_NSUB). y < 128: v blocks (VCHUNK rows each).
// y >= 128: ckv copy blocks (16382 float4 each) riding in the saturated grid.
__global__ void __launch_bounds__(256, 4)
v_copy_wv(const float* __restrict__ up_cache, float* __restrict__ out_up,
          const float* __restrict__ ckv_cache, float* __restrict__ out_ckv) {
    int b = blockIdx.x, tid = threadIdx.x;
    if (blockIdx.y >= 128) {                         // ckv copy block
        int sub = blockIdx.y - 128;
        size_t start = (size_t)sub * CKV_PER_BLOCK;
        size_t end   = start + CKV_PER_BLOCK;
        const float4* src = (const float4*)ckv_cache + (size_t)b * CKV_F4_PER_B;
        float4*       dst = (float4*)out_ckv + (size_t)b * (STOT * LOWD / 4);
#pragma unroll 4
        for (size_t i = start + tid; i < end; i += 256)
            __stcs(dst + i, __ldcs(src + i));
        return;
    }
    __shared__ float sw[VCHUNK];
    int s0 = blockIdx.y * VCHUNK;
    if (tid < VCHUNK) sw[tid] = g_w[b * STOT + s0 + tid];
    __syncthreads();
    int rows = SPAST - s0; if (rows > VCHUNK) rows = VCHUNK;   // last block: 63 cache rows
    const float4* src = (const float4*)(up_cache + ((size_t)b * SPAST + s0) * 2 * DD) + 256 + tid;
    float4*       dst = (float4*)(out_up + ((size_t)b * STOT + s0) * 2 * DD) + 256 + tid;

    float4 a0 = make_float4(0.f,0.f,0.f,0.f), a1 = a0, a2 = a0, a3 = a0;
    int r = 0;
    for (; r + 8 <= rows; r += 8) {
        float4 v[8];
#pragma unroll
        for (int j = 0; j < 8; j++) v[j] = __ldcs(src + (size_t)(r + j) * 512);
#pragma unroll
        for (int j = 0; j < 8; j++) __stcs(dst + (size_t)(r + j) * 512, v[j]);
#pragma unroll
        for (int j = 0; j < 4; j++) {
            float wa = sw[r + 2 * j], wb = sw[r + 2 * j + 1];
            float4 va = v[2 * j], vb = v[2 * j + 1];
            float4* A = (j == 0) ? &a0 : (j == 1) ? &a1 : (j == 2) ? &a2 : &a3;
            A->x = fmaf(wa, va.x, A->x); A->y = fmaf(wa, va.y, A->y);
            A->z = fmaf(wa, va.z, A->z); A->w = fmaf(wa, va.w, A->w);
            A->x = fmaf(wb, vb.x, A->x); A->y = fmaf(wb, vb.y, A->y);
            A->z = fmaf(wb, vb.z, A->z); A->w = fmaf(wb, vb.w, A->w);
        }
    }
    for (; r < rows; r++) {
        float4 v = __ldcs(src + (size_t)r * 512);
        __stcs(dst + (size_t)r * 512, v);
        float w = sw[r];
        a0.x = fmaf(w, v.x, a0.x); a0.y = fmaf(w, v.y, a0.y);
        a0.z = fmaf(w, v.z, a0.z); a0.w = fmaf(w, v.w, a0.w);
    }
    // current-token row (v already copied to out_up by fin_softmax; read from scratch)
    if (s0 + VCHUNK > SPAST) {
        float w = sw[SPAST - s0];
        float4 v = ((const float4*)(g_cur_up + b * 2 * DD + DD))[tid];
        a0.x = fmaf(w, v.x, a0.x); a0.y = fmaf(w, v.y, a0.y);
        a0.z = fmaf(w, v.z, a0.z); a0.w = fmaf(w, v.w, a0.w);
    }
    float4 a;
    a.x = (a0.x + a1.x) + (a2.x + a3.x);
    a.y = (a0.y + a1.y) + (a2.y + a3.y);
    a.z = (a0.z + a1.z) + (a2.z + a3.z);
    a.w = (a0.w + a1.w) + (a2.w + a3.w);
    float* dstA = g_attn + b * DD + 4 * tid;
    atomicAdd(dstA + 0, a.x);
    atomicAdd(dstA + 1, a.y);
    atomicAdd(dstA + 2, a.z);
    atomicAdd(dstA + 3, a.w);
}

// ------------------- out = attn @ Wo -------------------
// grid (4, 32): 1024 outputs tiled by 256; Din split 32.
__global__ void gemv_wo(const float* __restrict__ Wo, float* __restrict__ Y) {
    __shared__ float sx[BB * 32];
    int o = blockIdx.x * 256 + threadIdx.x;
    int d0 = blockIdx.y * 32;
    if (threadIdx.x < BB * 32) {
        int b = threadIdx.x >> 5, dd = threadIdx.x & 31;
        sx[threadIdx.x] = g_attn[b * DD + d0 + dd];
    }
    __syncthreads();
    float acc[BB];
#pragma unroll
    for (int b = 0; b < BB; b++) acc[b] = 0.f;
#pragma unroll
    for (int dd = 0; dd < 32; dd++) {
        float w = Wo[(size_t)(d0 + dd) * DD + o];
#pragma unroll
        for (int b = 0; b < BB; b++) acc[b] = fmaf(sx[(b << 5) + dd], w, acc[b]);
    }
#pragma unroll
    for (int b = 0; b < BB; b++) atomicAdd(&Y[b * DD + o], acc[b]);
}

// ------------------- launch -------------------
extern "C" void kernel_launch(void* const* d_in, const int* in_sizes, int n_in,
                              void* d_out, int out_size) {
    (void)in_sizes; (void)n_in; (void)out_size;
    const float* x        = (const float*)d_in[0];
    const float* ckv_c    = (const float*)d_in[1];
    const float* kr_c     = (const float*)d_in[2];
    const float* up_c     = (const float*)d_in[3];
    const float* Wdq      = (const float*)d_in[4];
    const float* Wuq      = (const float*)d_in[5];
    const float* Wqr      = (const float*)d_in[6];
    const float* Wdkv     = (const float*)d_in[7];
    const float* Wkr      = (const float*)d_in[8];
    const float* fup      = (const float*)d_in[9];
    const float* Wo       = (const float*)d_in[10];

    float* dout    = (float*)d_out;
    float* out_att = dout;                                     // [8,1,1024]
    float* out_ckv = dout + (size_t)BB * DD;                   // [8,8192,512]
    float* out_kr  = out_ckv + (size_t)BB * STOT * LOWD;       // [8,8192,1024]
    float* out_up  = out_kr  + (size_t)BB * STOT * DD;         // [8,8192,2048]

    zero_scratch<<<64, 256>>>(dout);

    // projection chain (2 fused launches, deep d-split for occupancy)
    proj1<<<dim3(10, 32), 256>>>(x, Wdkv, Wkr, Wdq);
    proj2<<<dim3(16, 32), 256>>>(Wuq, Wqr, fup);

    // streaming pass: kr/k_up copies + raw scores (ckv + v handled later)
    stream_score<<<BB * CPB, 256>>>(kr_c, up_c, out_kr, out_up);

    // current-token rows + cur score + exact softmax (merged)
    fin_softmax<<<BB, 256>>>(out_ckv, out_kr, out_up);

    // v copy + w·v accumulation + ckv copy, all in one saturated kernel
    v_copy_wv<<<dim3(BB, 128 + CKV_NSUB), 256>>>(up_c, out_up, ckv_c, out_ckv);

    // out = attn @ Wo
    gemv_wo<<<dim3(4, 32), 256>>>(Wo, out_att);
}

// round 17
// speedup vs baseline: 1.2724x; 1.0277x over previous
#include <cuda_runtime.h>
#include <math.h>

#define BB 8
#define DD 1024
#define LOWD 512
#define SPAST 8191
#define STOT 8192
#define CPB 256           // chunks (blocks) per batch
#define CHUNK 32          // rows per block
#define NWARP 8
#define SCALE 0.02209708691207961f  // 1/sqrt(2*1024)
#define VCHUNK 64         // rows per v_copy_wv block

// ------------------- device scratch (no allocations allowed) -------------------
__device__ float g_cur_ckv[BB*LOWD];
__device__ float g_cur_kr [BB*DD];
__device__ float g_cur_up [BB*2*DD];
__device__ float g_Cq  [BB*DD];
__device__ float g_Qc  [BB*DD];
__device__ float g_Qr  [BB*DD];
__device__ float g_score[BB*STOT];
__device__ float g_w    [BB*STOT];
__device__ float g_attn [BB*DD];

// ------------------- zero scratch + out_att region -------------------
__global__ void zero_scratch(float* __restrict__ dout) {
    int i = blockIdx.x * 256 + threadIdx.x;           // grid: 64*256 = 16384
    if (i < BB*LOWD)  g_cur_ckv[i] = 0.f;
    if (i < BB*DD) { g_cur_kr[i] = 0.f; g_Cq[i] = 0.f; g_Qc[i] = 0.f;
                     g_Qr[i] = 0.f; g_attn[i] = 0.f; }
    if (i < BB*2*DD)  g_cur_up[i] = 0.f;
    if (i < BB*DD)    dout[i] = 0.f;
}

// ------------------- stage 1: [cur_ckv | cur_kr | Cq] = x @ [Wdkv | Wkr | Wdq] --------
// grid (10, 32): 2560 outputs tiled by 256; Din=1024 split 32 (32 each); atomic accum.
__global__ void proj1(const float* __restrict__ x,
                      const float* __restrict__ Wdkv, const float* __restrict__ Wkr,
                      const float* __restrict__ Wdq) {
    __shared__ float sx[BB * 32];
    int og = blockIdx.x * 256 + threadIdx.x;         // 0..2559
    int d0 = blockIdx.y * 32;
    if (threadIdx.x < BB * 32) {
        int b = threadIdx.x >> 5, dd = threadIdx.x & 31;
        sx[threadIdx.x] = x[b * DD + d0 + dd];
    }
    __syncthreads();
    const float* W; float* Y; int O; int col;
    if (og < 512)       { W = Wdkv; Y = g_cur_ckv; O = LOWD; col = og; }
    else if (og < 1536) { W = Wkr;  Y = g_cur_kr;  O = DD;   col = og - 512; }
    else                { W = Wdq;  Y = g_Cq;      O = DD;   col = og - 1536; }
    float acc[BB];
#pragma unroll
    for (int b = 0; b < BB; b++) acc[b] = 0.f;
#pragma unroll
    for (int dd = 0; dd < 32; dd++) {
        float w = W[(size_t)(d0 + dd) * O + col];
#pragma unroll
        for (int b = 0; b < BB; b++) acc[b] = fmaf(sx[(b << 5) + dd], w, acc[b]);
    }
#pragma unroll
    for (int b = 0; b < BB; b++) atomicAdd(&Y[b * O + col], acc[b]);
}

// ------------------- stage 2: [Qc | Qr] = Cq @ [Wuq|Wqr]; cur_up = cur_ckv @ fup -------
// grid (16, 32): 4096 outputs tiled by 256. Ranges align to block boundaries.
__global__ void proj2(const float* __restrict__ Wuq, const float* __restrict__ Wqr,
                      const float* __restrict__ fup) {
    __shared__ float sx[BB * 32];
    int og = blockIdx.x * 256 + threadIdx.x;         // 0..4095
    const float* W; const float* X; float* Y; int O, col, Din;
    if (og < 1024)      { W = Wuq; X = g_Cq;      Y = g_Qc;     O = DD;     col = og;        Din = DD;   }
    else if (og < 2048) { W = Wqr; X = g_Cq;      Y = g_Qr;     O = DD;     col = og - 1024; Din = DD;   }
    else                { W = fup; X = g_cur_ckv; Y = g_cur_up; O = 2 * DD; col = og - 2048; Din = LOWD; }
    int dchunk = Din >> 5;                            // 32 or 16
    int d0 = blockIdx.y * dchunk;
    if (threadIdx.x < BB * dchunk) {
        int b = threadIdx.x / dchunk, dd = threadIdx.x - b * dchunk;
        sx[b * dchunk + dd] = X[b * Din + d0 + dd];
    }
    __syncthreads();
    float acc[BB];
#pragma unroll
    for (int b = 0; b < BB; b++) acc[b] = 0.f;
#pragma unroll 16
    for (int dd = 0; dd < dchunk; dd++) {
        float w = W[(size_t)(d0 + dd) * O + col];
#pragma unroll
        for (int b = 0; b < BB; b++) acc[b] = fmaf(sx[b * dchunk + dd], w, acc[b]);
    }
#pragma unroll
    for (int b = 0; b < BB; b++) atomicAdd(&Y[b * O + col], acc[b]);
}

// ------------------- main streaming kernel: ckv/kr/k_up copy + raw scores ---------------
// R11 operating point: in-block ckv copy, 4-deep load batching (measured 204.8us, 79.7%).
__global__ void __launch_bounds__(256)
stream_score(const float* __restrict__ ckv_cache, const float* __restrict__ kr_cache,
             const float* __restrict__ up_cache,
             float* __restrict__ out_ckv, float* __restrict__ out_kr, float* __restrict__ out_up) {
    __shared__ float4 sqc[DD / 4];                   // 4 KB
    __shared__ float4 sqr[DD / 4];                   // 4 KB
    int b    = blockIdx.x / CPB;
    int c    = blockIdx.x % CPB;
    int warp = threadIdx.x >> 5;
    int lane = threadIdx.x & 31;
    int s0   = c * CHUNK;
    int rows = SPAST - s0; if (rows > CHUNK) rows = CHUNK;

    // --- q into shared ---
    sqc[threadIdx.x] = ((const float4*)(g_Qc + b * DD))[threadIdx.x];
    sqr[threadIdx.x] = ((const float4*)(g_Qr + b * DD))[threadIdx.x];

    // --- ckv copy: flat, fully coalesced, independent iterations ---
    {
        const float4* src = (const float4*)(ckv_cache + (size_t)b * SPAST * LOWD) + (size_t)s0 * 128;
        float4*       dst = (float4*)(out_ckv + (size_t)b * STOT * LOWD) + (size_t)s0 * 128;
        int total = rows * 128;
#pragma unroll 4
        for (int i = threadIdx.x; i < total; i += 256)
            __stcs(dst + i, __ldcs(src + i));
    }
    __syncthreads();

    // --- per-warp rows: k_up + kr copy + dot (4-deep explicit load batching) ---
    for (int i = warp; i < rows; i += NWARP) {
        int s = s0 + i;
        const float4* u4 = (const float4*)(up_cache + ((size_t)b * SPAST + s) * 2 * DD);
        const float4* k4 = (const float4*)(kr_cache + ((size_t)b * SPAST + s) * DD);
        float4* ou4 = (float4*)(out_up + ((size_t)b * STOT + s) * 2 * DD);
        float4* ok4 = (float4*)(out_kr + ((size_t)b * STOT + s) * DD);

        float part = 0.f;
#pragma unroll
        for (int h = 0; h < 2; h++) {                // k_up half: 2 batches of 4
            float4 t[4];
#pragma unroll
            for (int j = 0; j < 4; j++) t[j] = __ldcs(u4 + lane + 32 * (4 * h + j));
#pragma unroll
            for (int j = 0; j < 4; j++) {
                __stcs(ou4 + lane + 32 * (4 * h + j), t[j]);
                float4 q = sqc[lane + 32 * (4 * h + j)];
                part += t[j].x * q.x + t[j].y * q.y + t[j].z * q.z + t[j].w * q.w;
            }
        }
#pragma unroll
        for (int h = 0; h < 2; h++) {                // kr: 2 batches of 4
            float4 t[4];
#pragma unroll
            for (int j = 0; j < 4; j++) t[j] = __ldcs(k4 + lane + 32 * (4 * h + j));
#pragma unroll
            for (int j = 0; j < 4; j++) {
                __stcs(ok4 + lane + 32 * (4 * h + j), t[j]);
                float4 q = sqr[lane + 32 * (4 * h + j)];
                part += t[j].x * q.x + t[j].y * q.y + t[j].z * q.z + t[j].w * q.w;
            }
        }
#pragma unroll
        for (int off = 16; off; off >>= 1) part += __shfl_xor_sync(0xffffffffu, part, off);
        if (lane == 0) g_score[b * STOT + s] = part * SCALE;
    }
}

// ------------------- current token rows + cur score + exact softmax (merged) ------------
__global__ void fin_softmax(float* __restrict__ out_ckv, float* __restrict__ out_kr,
                            float* __restrict__ out_up) {
    int b = blockIdx.x, tid = threadIdx.x;
    // copy new rows into position s = SPAST
    {
        const float4* cc = (const float4*)(g_cur_ckv + b * LOWD);
        float4* oc = (float4*)(out_ckv + ((size_t)b * STOT + SPAST) * LOWD);
        for (int i = tid; i < LOWD / 4; i += 256) oc[i] = cc[i];
        const float4* ck = (const float4*)(g_cur_kr + b * DD);
        float4* ok = (float4*)(out_kr + ((size_t)b * STOT + SPAST) * DD);
        for (int i = tid; i < DD / 4; i += 256) ok[i] = ck[i];
        const float4* cu = (const float4*)(g_cur_up + b * 2 * DD);
        float4* ou = (float4*)(out_up + ((size_t)b * STOT + SPAST) * 2 * DD);
        for (int i = tid; i < 2 * DD / 4; i += 256) ou[i] = cu[i];
    }
    // current-token raw score
    float part = 0.f;
    for (int i = tid; i < DD; i += 256) part += g_Qc[b * DD + i] * g_cur_up[b * 2 * DD + i];
    for (int i = tid; i < DD; i += 256) part += g_Qr[b * DD + i] * g_cur_kr[b * DD + i];
    __shared__ float sred[256];
    __shared__ float sM, sL;
    sred[tid] = part; __syncthreads();
    for (int s = 128; s; s >>= 1) { if (tid < s) sred[tid] += sred[tid + s]; __syncthreads(); }
    if (tid == 0) g_score[b * STOT + SPAST] = sred[0] * SCALE;
    __syncthreads();
    // exact softmax over all 8192 scores
    float M = -1e30f;
    for (int i = tid; i < STOT; i += 256) M = fmaxf(M, g_score[b * STOT + i]);
    sred[tid] = M; __syncthreads();
    for (int s = 128; s; s >>= 1) { if (tid < s) sred[tid] = fmaxf(sred[tid], sred[tid + s]); __syncthreads(); }
    if (tid == 0) sM = sred[0];
    __syncthreads();
    M = sM;
    float L = 0.f;
    for (int i = tid; i < STOT; i += 256) {
        float e = __expf(g_score[b * STOT + i] - M);
        g_w[b * STOT + i] = e;
        L += e;
    }
    sred[tid] = L; __syncthreads();
    for (int s = 128; s; s >>= 1) { if (tid < s) sred[tid] += sred[tid + s]; __syncthreads(); }
    if (tid == 0) sL = sred[0];
    __syncthreads();
    float inv = 1.f / sL;
    for (int i = tid; i < STOT; i += 256) g_w[b * STOT + i] *= inv;
}

// ------------------- v copy + attn accumulation fused (post-softmax) --------------------
// grid (BB, 128). 8-deep load batching; 4 CTAs/SM pinned.
__global__ void __launch_bounds__(256, 4)
v_copy_wv(const float* __restrict__ up_cache, float* __restrict__ out_up) {
    __shared__ float sw[VCHUNK];
    int b = blockIdx.x, tid = threadIdx.x;
    int s0 = blockIdx.y * VCHUNK;
    if (tid < VCHUNK) sw[tid] = g_w[b * STOT + s0 + tid];
    __syncthreads();
    int rows = SPAST - s0; if (rows > VCHUNK) rows = VCHUNK;   // last block: 63 cache rows
    const float4* src = (const float4*)(up_cache + ((size_t)b * SPAST + s0) * 2 * DD) + 256 + tid;
    float4*       dst = (float4*)(out_up + ((size_t)b * STOT + s0) * 2 * DD) + 256 + tid;

    float4 a0 = make_float4(0.f,0.f,0.f,0.f), a1 = a0, a2 = a0, a3 = a0;
    int r = 0;
    for (; r + 8 <= rows; r += 8) {
        float4 v[8];
#pragma unroll
        for (int j = 0; j < 8; j++) v[j] = __ldcs(src + (size_t)(r + j) * 512);
#pragma unroll
        for (int j = 0; j < 8; j++) __stcs(dst + (size_t)(r + j) * 512, v[j]);
#pragma unroll
        for (int j = 0; j < 4; j++) {
            float wa = sw[r + 2 * j], wb = sw[r + 2 * j + 1];
            float4 va = v[2 * j], vb = v[2 * j + 1];
            float4* A = (j == 0) ? &a0 : (j == 1) ? &a1 : (j == 2) ? &a2 : &a3;
            A->x = fmaf(wa, va.x, A->x); A->y = fmaf(wa, va.y, A->y);
            A->z = fmaf(wa, va.z, A->z); A->w = fmaf(wa, va.w, A->w);
            A->x = fmaf(wb, vb.x, A->x); A->y = fmaf(wb, vb.y, A->y);
            A->z = fmaf(wb, vb.z, A->z); A->w = fmaf(wb, vb.w, A->w);
        }
    }
    for (; r < rows; r++) {
        float4 v = __ldcs(src + (size_t)r * 512);
        __stcs(dst + (size_t)r * 512, v);
        float w = sw[r];
        a0.x = fmaf(w, v.x, a0.x); a0.y = fmaf(w, v.y, a0.y);
        a0.z = fmaf(w, v.z, a0.z); a0.w = fmaf(w, v.w, a0.w);
    }
    // current-token row (v already copied to out_up by fin_softmax; read from scratch)
    if (s0 + VCHUNK > SPAST) {
        float w = sw[SPAST - s0];
        float4 v = ((const float4*)(g_cur_up + b * 2 * DD + DD))[tid];
        a0.x = fmaf(w, v.x, a0.x); a0.y = fmaf(w, v.y, a0.y);
        a0.z = fmaf(w, v.z, a0.z); a0.w = fmaf(w, v.w, a0.w);
    }
    float4 a;
    a.x = (a0.x + a1.x) + (a2.x + a3.x);
    a.y = (a0.y + a1.y) + (a2.y + a3.y);
    a.z = (a0.z + a1.z) + (a2.z + a3.z);
    a.w = (a0.w + a1.w) + (a2.w + a3.w);
    float* dstA = g_attn + b * DD + 4 * tid;
    atomicAdd(dstA + 0, a.x);
    atomicAdd(dstA + 1, a.y);
    atomicAdd(dstA + 2, a.z);
    atomicAdd(dstA + 3, a.w);
}

// ------------------- out = attn @ Wo -------------------
// grid (4, 32): 1024 outputs tiled by 256; Din split 32.
__global__ void gemv_wo(const float* __restrict__ Wo, float* __restrict__ Y) {
    __shared__ float sx[BB * 32];
    int o = blockIdx.x * 256 + threadIdx.x;
    int d0 = blockIdx.y * 32;
    if (threadIdx.x < BB * 32) {
        int b = threadIdx.x >> 5, dd = threadIdx.x & 31;
        sx[threadIdx.x] = g_attn[b * DD + d0 + dd];
    }
    __syncthreads();
    float acc[BB];
#pragma unroll
    for (int b = 0; b < BB; b++) acc[b] = 0.f;
#pragma unroll
    for (int dd = 0; dd < 32; dd++) {
        float w = Wo[(size_t)(d0 + dd) * DD + o];
#pragma unroll
        for (int b = 0; b < BB; b++) acc[b] = fmaf(sx[(b << 5) + dd], w, acc[b]);
    }
#pragma unroll
    for (int b = 0; b < BB; b++) atomicAdd(&Y[b * DD + o], acc[b]);
}

// ------------------- launch (single stream, no events — capture-safe) -------------------
extern "C" void kernel_launch(void* const* d_in, const int* in_sizes, int n_in,
                              void* d_out, int out_size) {
    (void)in_sizes; (void)n_in; (void)out_size;
    const float* x        = (const float*)d_in[0];
    const float* ckv_c    = (const float*)d_in[1];
    const float* kr_c     = (const float*)d_in[2];
    const float* up_c     = (const float*)d_in[3];
    const float* Wdq      = (const float*)d_in[4];
    const float* Wuq      = (const float*)d_in[5];
    const float* Wqr      = (const float*)d_in[6];
    const float* Wdkv     = (const float*)d_in[7];
    const float* Wkr      = (const float*)d_in[8];
    const float* fup      = (const float*)d_in[9];
    const float* Wo       = (const float*)d_in[10];

    float* dout    = (float*)d_out;
    float* out_att = dout;                                     // [8,1,1024]
    float* out_ckv = dout + (size_t)BB * DD;                   // [8,8192,512]
    float* out_kr  = out_ckv + (size_t)BB * STOT * LOWD;       // [8,8192,1024]
    float* out_up  = out_kr  + (size_t)BB * STOT * DD;         // [8,8192,2048]

    zero_scratch<<<64, 256>>>(dout);

    // projection chain (2 fused launches, deep d-split for occupancy)
    proj1<<<dim3(10, 32), 256>>>(x, Wdkv, Wkr, Wdq);
    proj2<<<dim3(16, 32), 256>>>(Wuq, Wqr, fup);

    // big streaming pass: ckv/kr/k_up copies + raw scores (v deferred)
    stream_score<<<BB * CPB, 256>>>(ckv_c, kr_c, up_c, out_ckv, out_kr, out_up);

    // current-token rows + cur score + exact softmax (merged)
    fin_softmax<<<BB, 256>>>(out_ckv, out_kr, out_up);

    // v copy + attn accumulation in one pass (reads v exactly once)
    v_copy_wv<<<dim3(BB, 128), 256>>>(up_c, out_up);

    // out = attn @ Wo
    gemv_wo<<<dim3(4, 32), 256>>>(Wo, out_att);
}